// round 5
// baseline (speedup 1.0000x reference)
#include <cuda_runtime.h>
#include <cuda_fp16.h>
#include <cstdint>

#define NB 4
#define ND 128
#define NK 256
#define NS 256
#define NJ 257
#define NO 256
#define TOUT 32768
#define NTILE (NB * NJ)          // 1028
#define GRID_MAIN 148

// ---------------- scratch ----------------
__device__ __half g_Af[(size_t)NB*NJ*128*ND];   // presummed OLA frames, fp16 [b][j][p][d]
__device__ __half g_W1f[NO*ND];                 // [o][d]
__device__ __half g_W2f[NO*ND];                 // [o2][e]

// smem map (bytes)
#define SM_B1 0
#define SM_B2 1024
#define SM_W1 2048
#define SM_W2 (SM_W1 + 65536)
#define SM_A  (SM_W2 + 65536)     // 32KB A (double-duty: prefetched per tile)
#define SM_Z  (SM_A + 32768)      // 64KB Z (c0|c1)
#define SM_TOT (SM_Z + 65536)     // 231424

__device__ __forceinline__ uint32_t smem_u32(const void* p) {
    uint32_t a;
    asm("{ .reg .u64 t; cvta.to.shared.u64 t, %1; cvt.u32.u64 %0, t; }" : "=r"(a) : "l"(p));
    return a;
}
__device__ __forceinline__ uint32_t swz(uint32_t row, uint32_t byteCol) {
    return row * 256u + ((((byteCol >> 4) ^ (row & 7)) << 4) | (byteCol & 15));
}
#define LDSM4(r0,r1,r2,r3,addr) \
    asm volatile("ldmatrix.sync.aligned.m8n8.x4.shared.b16 {%0,%1,%2,%3}, [%4];" \
        : "=r"(r0),"=r"(r1),"=r"(r2),"=r"(r3) : "r"(addr))
#define CP16(dst, src) \
    asm volatile("cp.async.cg.shared.global [%0], [%1], 16;" :: "r"(dst), "l"(src) : "memory")
#define CP_COMMIT() asm volatile("cp.async.commit_group;" ::: "memory")
#define CP_WAIT0()  asm volatile("cp.async.wait_group 0;" ::: "memory")

__device__ __forceinline__ void mma16816(float d[4], const uint32_t a[4], uint32_t b0, uint32_t b1) {
    asm volatile("mma.sync.aligned.m16n8k16.row.col.f32.f16.f16.f32 "
        "{%0,%1,%2,%3}, {%4,%5,%6,%7}, {%8,%9}, {%0,%1,%2,%3};"
        : "+f"(d[0]), "+f"(d[1]), "+f"(d[2]), "+f"(d[3])
        : "r"(a[0]), "r"(a[1]), "r"(a[2]), "r"(a[3]), "r"(b0), "r"(b1));
}

// ---------------- prep: W fp16 convert + OLA-presummed A (unchanged from R4) ----------------
__global__ void prep_all(const float* __restrict__ x, const float* __restrict__ pw_ptr,
                         const float* __restrict__ w1, const float* __restrict__ w2)
{
    int tx = threadIdx.x, ty = threadIdx.y;
    int tid = ty * 32 + tx;
    if (blockIdx.z == NB * 128) {
        int flat = (blockIdx.x * 4 + blockIdx.y) * 256 + tid;
        for (; flat < 2 * NO * ND; flat += 36 * 256) {
            if (flat < NO * ND) g_W1f[flat] = __float2half_rn(w1[flat]);
            else                g_W2f[flat - NO * ND] = __float2half_rn(w2[flat - NO * ND]);
        }
        return;
    }
    __shared__ float t[32][33];
    int b = blockIdx.z >> 7, p = blockIdx.z & 127;
    int j0 = blockIdx.x * 32, d0 = blockIdx.y * 32;
    float pw = *pw_ptr;
#pragma unroll
    for (int i = 0; i < 4; i++) {
        int d = d0 + ty + i * 8;
        int jj = j0 + tx;
        float acc = 0.f;
        if (jj < 256) {
            float v = x[(((size_t)b * ND + d) * NK + p) * NS + jj];
            acc += (v >= 0.f) ? v : pw * v;
        }
        if (jj >= 1 && jj <= 256) {
            float v = x[(((size_t)b * ND + d) * NK + p + 128) * NS + jj - 1];
            acc += (v >= 0.f) ? v : pw * v;
        }
        t[ty + i * 8][tx] = acc;
    }
    __syncthreads();
#pragma unroll
    for (int i = 0; i < 4; i++) {
        int jl = ty + i * 8;
        int jj = j0 + jl;
        if (jj <= 256) {
            g_Af[(((size_t)b * NJ + jj) * 128 + p) * ND + d0 + tx] = __float2half_rn(t[tx][jl]);
        }
    }
}

// ---------------- persistent fused main kernel ----------------
__global__ __launch_bounds__(512, 1) void main_kernel(
    const float* __restrict__ b1g, const float* __restrict__ b2g, float* __restrict__ out)
{
    extern __shared__ char smc[];
    uint32_t sb = smem_u32(smc);
    float* s_b1 = (float*)(smc + SM_B1);
    float* s_b2 = (float*)(smc + SM_B2);
    int tid = threadIdx.x, w = tid >> 5, lane = tid & 31;
    int pw = (w & 3) * 32, ow = (w >> 2) * 64;

    if (tid < 256) { s_b1[tid] = b1g[tid]; s_b2[tid] = b2g[tid]; }

    // ---- prologue: W1+W2 resident + first A, all via cp.async ----
    int g = blockIdx.x;
    {
        const uint4* w14 = (const uint4*)g_W1f;
        const uint4* w24 = (const uint4*)g_W2f;
#pragma unroll
        for (int q = 0; q < 8; q++) {
            int idx = tid + q * 512;
            uint32_t off = swz(idx >> 4, (idx & 15) << 4);
            CP16(sb + SM_W1 + off, (const void*)(w14 + idx));
            CP16(sb + SM_W2 + off, (const void*)(w24 + idx));
        }
        if (g < NTILE) {
            const uint4* a4 = (const uint4*)(g_Af + (size_t)g * (128 * ND));
#pragma unroll
            for (int q = 0; q < 4; q++) {
                int idx = tid + q * 512;
                CP16(sb + SM_A + swz(idx >> 4, (idx & 15) << 4), (const void*)(a4 + idx));
            }
        }
        CP_COMMIT();
        CP_WAIT0();
    }
    __syncthreads();

    // ldmatrix lane addressing
    int ar = pw + (lane & 15);
    uint32_t acb = (uint32_t)(lane >> 4) << 4;
    int br = ow + ((lane >> 3) & 1) * 8 + (lane & 7);
    uint32_t bcb = (uint32_t)((lane >> 4) & 1) << 4;
    uint32_t uW1 = sb + SM_W1, uW2 = sb + SM_W2, uA = sb + SM_A;
    int lr = lane >> 2, lc = (lane & 3) << 1;
    int cW = ow >> 7;
    char* zB = smc + SM_Z + cW * 32768;

    float acc[2][8][4];

    // ---- persistent tile loop ----
    for (; g < NTILE; g += GRID_MAIN) {
        int b = g / NJ, j = g - b * NJ;

        // ---- GEMM1: D1[p=128][o=256] = A[p][d] * W1[o][d] ----
#pragma unroll
        for (int mt = 0; mt < 2; mt++)
#pragma unroll
            for (int nt = 0; nt < 8; nt++)
#pragma unroll
                for (int q = 0; q < 4; q++) acc[mt][nt][q] = 0.f;
#pragma unroll
        for (int ks = 0; ks < 8; ks++) {
            uint32_t kb = (uint32_t)ks * 32;
            uint32_t a[2][4], bf[4][4];
#pragma unroll
            for (int mt = 0; mt < 2; mt++)
                LDSM4(a[mt][0], a[mt][1], a[mt][2], a[mt][3], uA + swz(ar + mt * 16, kb + acb));
#pragma unroll
            for (int ng = 0; ng < 4; ng++)
                LDSM4(bf[ng][0], bf[ng][1], bf[ng][2], bf[ng][3], uW1 + swz(br + ng * 16, kb + bcb));
#pragma unroll
            for (int mt = 0; mt < 2; mt++)
#pragma unroll
                for (int ng = 0; ng < 4; ng++) {
                    mma16816(acc[mt][2 * ng],     a[mt], bf[ng][0], bf[ng][2]);
                    mma16816(acc[mt][2 * ng + 1], a[mt], bf[ng][1], bf[ng][3]);
                }
        }
        __syncthreads();   // A consumed; prev-tile Z reads also complete

        // ---- prefetch next tile's A (overlaps epi1 + GEMM2 + stores) ----
        {
            int gn = g + GRID_MAIN;
            if (gn < NTILE) {
                const uint4* a4 = (const uint4*)(g_Af + (size_t)gn * (128 * ND));
#pragma unroll
                for (int q = 0; q < 4; q++) {
                    int idx = tid + q * 512;
                    CP16(sb + SM_A + swz(idx >> 4, (idx & 15) << 4), (const void*)(a4 + idx));
                }
            }
            CP_COMMIT();
        }

        // ---- epilogue1: Z = relu(D1 + nf*b1) -> fp16 in SM_Z ----
        float nf = (j == 0 || j == 256) ? 1.f : 2.f;
#pragma unroll
        for (int mt = 0; mt < 2; mt++) {
#pragma unroll
            for (int nt = 0; nt < 8; nt++) {
                int o = ow + nt * 8 + lc;
                int e = o & 127;
                float b0v = nf * s_b1[o], b1v = nf * s_b1[o + 1];
#pragma unroll
                for (int hf = 0; hf < 2; hf++) {
                    int p = pw + mt * 16 + lr + hf * 8;
                    __half2 hv;
                    hv.x = __float2half_rn(fmaxf(acc[mt][nt][hf * 2]     + b0v, 0.f));
                    hv.y = __float2half_rn(fmaxf(acc[mt][nt][hf * 2 + 1] + b1v, 0.f));
                    *(uint32_t*)(zB + swz((uint32_t)p, (uint32_t)e << 1)) = *(uint32_t*)&hv;
                }
            }
        }
        __syncthreads();

        // ---- GEMM2 per channel + out stores ----
        int l0 = j * 128 - 64;
#pragma unroll 1
        for (int c = 0; c < 2; c++) {
            uint32_t uZ = sb + SM_Z + c * 32768;
#pragma unroll
            for (int mt = 0; mt < 2; mt++)
#pragma unroll
                for (int nt = 0; nt < 8; nt++)
#pragma unroll
                    for (int q = 0; q < 4; q++) acc[mt][nt][q] = 0.f;
#pragma unroll
            for (int ks = 0; ks < 8; ks++) {
                uint32_t kb = (uint32_t)ks * 32;
                uint32_t a[2][4], bf[4][4];
#pragma unroll
                for (int mt = 0; mt < 2; mt++)
                    LDSM4(a[mt][0], a[mt][1], a[mt][2], a[mt][3], uZ + swz(ar + mt * 16, kb + acb));
#pragma unroll
                for (int ng = 0; ng < 4; ng++)
                    LDSM4(bf[ng][0], bf[ng][1], bf[ng][2], bf[ng][3], uW2 + swz(br + ng * 16, kb + bcb));
#pragma unroll
                for (int mt = 0; mt < 2; mt++)
#pragma unroll
                    for (int ng = 0; ng < 4; ng++) {
                        mma16816(acc[mt][2 * ng],     a[mt], bf[ng][0], bf[ng][2]);
                        mma16816(acc[mt][2 * ng + 1], a[mt], bf[ng][1], bf[ng][3]);
                    }
            }
            float* ob = out + (size_t)(b * 2 + c) * NO * TOUT;
#pragma unroll
            for (int mt = 0; mt < 2; mt++) {
#pragma unroll
                for (int hf = 0; hf < 2; hf++) {
                    int p = pw + mt * 16 + lr + hf * 8;
                    int l = l0 + p;
                    if (l >= 0 && l < TOUT) {
#pragma unroll
                        for (int nt = 0; nt < 8; nt++) {
                            int o2 = ow + nt * 8 + lc;
                            ob[(size_t)o2 * TOUT + l]       = acc[mt][nt][hf * 2]     + s_b2[o2];
                            ob[(size_t)(o2 + 1) * TOUT + l] = acc[mt][nt][hf * 2 + 1] + s_b2[o2 + 1];
                        }
                    }
                }
            }
        }
        CP_WAIT0();        // next A landed
        __syncthreads();   // Z reads done before next epi1; A visible to all
    }
}

// ---------------------------------------------------------------------------
extern "C" void kernel_launch(void* const* d_in, const int* in_sizes, int n_in,
                              void* d_out, int out_size) {
    const float* x  = (const float*)d_in[0];
    const float* pw = (const float*)d_in[1];
    const float* w1 = (const float*)d_in[2];
    const float* b1 = (const float*)d_in[3];
    const float* w2 = (const float*)d_in[4];
    const float* b2 = (const float*)d_in[5];
    float* out = (float*)d_out;

    cudaFuncSetAttribute(main_kernel, cudaFuncAttributeMaxDynamicSharedMemorySize, SM_TOT);

    prep_all<<<dim3(9, 4, NB * 128 + 1), dim3(32, 8)>>>(x, pw, w1, w2);
    main_kernel<<<GRID_MAIN, 512, SM_TOT>>>(b1, b2, out);
}

// round 6
// speedup vs baseline: 1.2946x; 1.2946x over previous
#include <cuda_runtime.h>
#include <cuda_fp16.h>
#include <cstdint>

#define NB 4
#define ND 128
#define NK 256
#define NS 256
#define NJ 257
#define NO 256
#define TOUT 32768

// ---------------- scratch ----------------
__device__ __half g_Af[(size_t)NB*NJ*128*ND];   // presummed OLA frames, fp16 [b][j][p][d]
__device__ __half g_W1f[NO*ND];                 // [o][d]
__device__ __half g_W2f[NO*ND];                 // [o2][e]

// smem map
#define SM_B1 0
#define SM_B2 1024
#define SM_W  2048                    // 64KB: W1 then W2
#define SM_AZ (2048 + 65536)          // 64KB: A (32K) then Z (c0|c1, 32K each)
#define SM_TOT (SM_AZ + 65536)        // 133120 B

__device__ __forceinline__ uint32_t smem_u32(const void* p) {
    uint32_t a;
    asm("{ .reg .u64 t; cvta.to.shared.u64 t, %1; cvt.u32.u64 %0, t; }" : "=r"(a) : "l"(p));
    return a;
}
__device__ __forceinline__ uint32_t swz(uint32_t row, uint32_t byteCol) {
    return row * 256u + ((((byteCol >> 4) ^ (row & 7)) << 4) | (byteCol & 15));
}
#define LDSM4(r0,r1,r2,r3,addr) \
    asm volatile("ldmatrix.sync.aligned.m8n8.x4.shared.b16 {%0,%1,%2,%3}, [%4];" \
        : "=r"(r0),"=r"(r1),"=r"(r2),"=r"(r3) : "r"(addr))

__device__ __forceinline__ void mma16816(float d[4], const uint32_t a[4], uint32_t b0, uint32_t b1) {
    asm volatile("mma.sync.aligned.m16n8k16.row.col.f32.f16.f16.f32 "
        "{%0,%1,%2,%3}, {%4,%5,%6,%7}, {%8,%9}, {%0,%1,%2,%3};"
        : "+f"(d[0]), "+f"(d[1]), "+f"(d[2]), "+f"(d[3])
        : "r"(a[0]), "r"(a[1]), "r"(a[2]), "r"(a[3]), "r"(b0), "r"(b1));
}

// ---------------- prep: W fp16 convert + OLA-presummed A (proven in R4) ----------------
__global__ void prep_all(const float* __restrict__ x, const float* __restrict__ pw_ptr,
                         const float* __restrict__ w1, const float* __restrict__ w2)
{
    int tx = threadIdx.x, ty = threadIdx.y;
    int tid = ty * 32 + tx;
    if (blockIdx.z == NB * 128) {
        int flat = (blockIdx.x * 4 + blockIdx.y) * 256 + tid;
        for (; flat < 2 * NO * ND; flat += 36 * 256) {
            if (flat < NO * ND) g_W1f[flat] = __float2half_rn(w1[flat]);
            else                g_W2f[flat - NO * ND] = __float2half_rn(w2[flat - NO * ND]);
        }
        return;
    }
    __shared__ float t[32][33];
    int b = blockIdx.z >> 7, p = blockIdx.z & 127;
    int j0 = blockIdx.x * 32, d0 = blockIdx.y * 32;
    float pw = *pw_ptr;
#pragma unroll
    for (int i = 0; i < 4; i++) {
        int d = d0 + ty + i * 8;
        int jj = j0 + tx;
        float acc = 0.f;
        if (jj < 256) {
            float v = x[(((size_t)b * ND + d) * NK + p) * NS + jj];
            acc += (v >= 0.f) ? v : pw * v;
        }
        if (jj >= 1 && jj <= 256) {
            float v = x[(((size_t)b * ND + d) * NK + p + 128) * NS + jj - 1];
            acc += (v >= 0.f) ? v : pw * v;
        }
        t[ty + i * 8][tx] = acc;
    }
    __syncthreads();
#pragma unroll
    for (int i = 0; i < 4; i++) {
        int jl = ty + i * 8;
        int jj = j0 + jl;
        if (jj <= 256) {
            g_Af[(((size_t)b * NJ + jj) * 128 + p) * ND + d0 + tx] = __float2half_rn(t[tx][jl]);
        }
    }
}

// ---------------- fused main kernel (R4 structure, transposed GEMM2) ----------------
__global__ __launch_bounds__(512, 1) void main_kernel(
    const float* __restrict__ b1g, const float* __restrict__ b2g, float* __restrict__ out)
{
    extern __shared__ char smc[];
    uint32_t sb = smem_u32(smc);
    float* s_b1 = (float*)(smc + SM_B1);
    float* s_b2 = (float*)(smc + SM_B2);
    int tid = threadIdx.x, w = tid >> 5, lane = tid & 31;
    int j = blockIdx.x, b = blockIdx.y;
    int pw = (w & 3) * 32, ow = (w >> 2) * 64;

    if (tid < 256) { s_b1[tid] = b1g[tid]; s_b2[tid] = b2g[tid]; }

    // ---- W1 -> SM_W, A -> SM_AZ ----
    {
        const uint4* w4 = (const uint4*)g_W1f;
        for (int idx = tid; idx < 4096; idx += 512)
            *(uint4*)(smc + SM_W + swz(idx >> 4, (idx & 15) << 4)) = w4[idx];
        const uint4* a4 = (const uint4*)(g_Af + ((size_t)b * NJ + j) * (128 * ND));
        for (int idx = tid; idx < 2048; idx += 512)
            *(uint4*)(smc + SM_AZ + swz(idx >> 4, (idx & 15) << 4)) = a4[idx];
    }
    __syncthreads();

    // operand lane patterns
    int arow = lane & 15;                                 // a-pattern row within 16
    uint32_t acb = (uint32_t)(lane >> 4) << 4;
    int brow = ((lane >> 3) & 1) * 8 + (lane & 7);        // b-pattern row within 16
    uint32_t bcb = (uint32_t)((lane >> 4) & 1) << 4;
    uint32_t uW = sb + SM_W, uA = sb + SM_AZ;
    int lr = lane >> 2, lc = (lane & 3) << 1;

    float acc[2][8][4];

    // ---- GEMM1: D1[p=128][o=256] = A[p][d] * W1[o][d] (a=A, b=W1) ----
#pragma unroll
    for (int mt = 0; mt < 2; mt++)
#pragma unroll
        for (int nt = 0; nt < 8; nt++)
#pragma unroll
            for (int q = 0; q < 4; q++) acc[mt][nt][q] = 0.f;
    {
        int ar = pw + arow, br = ow + brow;
#pragma unroll
        for (int ks = 0; ks < 8; ks++) {
            uint32_t kb = (uint32_t)ks * 32;
            uint32_t a[2][4], bf[4][4];
#pragma unroll
            for (int mt = 0; mt < 2; mt++)
                LDSM4(a[mt][0], a[mt][1], a[mt][2], a[mt][3], uA + swz(ar + mt * 16, kb + acb));
#pragma unroll
            for (int ng = 0; ng < 4; ng++)
                LDSM4(bf[ng][0], bf[ng][1], bf[ng][2], bf[ng][3], uW + swz(br + ng * 16, kb + bcb));
#pragma unroll
            for (int mt = 0; mt < 2; mt++)
#pragma unroll
                for (int ng = 0; ng < 4; ng++) {
                    mma16816(acc[mt][2 * ng],     a[mt], bf[ng][0], bf[ng][2]);
                    mma16816(acc[mt][2 * ng + 1], a[mt], bf[ng][1], bf[ng][3]);
                }
        }
    }
    __syncthreads();   // W1/A reads complete

    // ---- epilogue1: Z = relu(D1 + nf*b1) -> fp16, rows=p, cols=e, channel blocks ----
    float nf = (j == 0 || j == 256) ? 1.f : 2.f;
    int cW = ow >> 7;
    char* zB = smc + SM_AZ + cW * 32768;
#pragma unroll
    for (int mt = 0; mt < 2; mt++) {
#pragma unroll
        for (int nt = 0; nt < 8; nt++) {
            int o = ow + nt * 8 + lc;
            int e = o & 127;
            float b0v = nf * s_b1[o], b1v = nf * s_b1[o + 1];
#pragma unroll
            for (int hf = 0; hf < 2; hf++) {
                int p = pw + mt * 16 + lr + hf * 8;
                __half2 hv;
                hv.x = __float2half_rn(fmaxf(acc[mt][nt][hf * 2]     + b0v, 0.f));
                hv.y = __float2half_rn(fmaxf(acc[mt][nt][hf * 2 + 1] + b1v, 0.f));
                *(uint32_t*)(zB + swz((uint32_t)p, (uint32_t)e << 1)) = *(uint32_t*)&hv;
            }
        }
    }
    // ---- W2 -> SM_W (W1 dead) ----
    {
        const uint4* w4 = (const uint4*)g_W2f;
        for (int idx = tid; idx < 4096; idx += 512)
            *(uint4*)(smc + SM_W + swz(idx >> 4, (idx & 15) << 4)) = w4[idx];
    }
    __syncthreads();

    // ---- GEMM2 (transposed): D2^T[o2=256][p=128] = W2[o2][e] * Z_c[p][e]
    //      a-operand = W2 (m = o2), b-operand = Z (n = p) -> coalesced v2 stores ----
    int o2w = (w & 7) * 32, pw2 = (w >> 3) * 64;
    int l0 = j * 128 - 64;
    int ar2 = o2w + arow, br2 = pw2 + brow;
#pragma unroll 1
    for (int c = 0; c < 2; c++) {
        uint32_t uZ = sb + SM_AZ + c * 32768;
#pragma unroll
        for (int mt = 0; mt < 2; mt++)
#pragma unroll
            for (int nt = 0; nt < 8; nt++)
#pragma unroll
                for (int q = 0; q < 4; q++) acc[mt][nt][q] = 0.f;
#pragma unroll
        for (int ks = 0; ks < 8; ks++) {
            uint32_t kb = (uint32_t)ks * 32;
            uint32_t a[2][4], bf[4][4];
#pragma unroll
            for (int mt = 0; mt < 2; mt++)
                LDSM4(a[mt][0], a[mt][1], a[mt][2], a[mt][3], uW + swz(ar2 + mt * 16, kb + acb));
#pragma unroll
            for (int ng = 0; ng < 4; ng++)
                LDSM4(bf[ng][0], bf[ng][1], bf[ng][2], bf[ng][3], uZ + swz(br2 + ng * 16, kb + bcb));
#pragma unroll
            for (int mt = 0; mt < 2; mt++)
#pragma unroll
                for (int ng = 0; ng < 4; ng++) {
                    mma16816(acc[mt][2 * ng],     a[mt], bf[ng][0], bf[ng][2]);
                    mma16816(acc[mt][2 * ng + 1], a[mt], bf[ng][1], bf[ng][3]);
                }
        }
        // ---- out epilogue: thread pair = (o2 row, two consecutive l) ----
        float* ob = out + (size_t)(b * 2 + c) * NO * TOUT;
#pragma unroll
        for (int mt = 0; mt < 2; mt++) {
#pragma unroll
            for (int hf = 0; hf < 2; hf++) {
                int o2 = o2w + mt * 16 + lr + hf * 8;
                float bo = s_b2[o2];
                float* orow = ob + (size_t)o2 * TOUT + l0;
#pragma unroll
                for (int nt = 0; nt < 8; nt++) {
                    int p = pw2 + nt * 8 + lc;
                    int l = l0 + p;
                    if (l >= 0 && l < TOUT) {
                        float2 v;
                        v.x = acc[mt][nt][hf * 2]     + bo;
                        v.y = acc[mt][nt][hf * 2 + 1] + bo;
                        *(float2*)(orow + p) = v;
                    }
                }
            }
        }
    }
}

// ---------------------------------------------------------------------------
extern "C" void kernel_launch(void* const* d_in, const int* in_sizes, int n_in,
                              void* d_out, int out_size) {
    const float* x  = (const float*)d_in[0];
    const float* pw = (const float*)d_in[1];
    const float* w1 = (const float*)d_in[2];
    const float* b1 = (const float*)d_in[3];
    const float* w2 = (const float*)d_in[4];
    const float* b2 = (const float*)d_in[5];
    float* out = (float*)d_out;

    cudaFuncSetAttribute(main_kernel, cudaFuncAttributeMaxDynamicSharedMemorySize, SM_TOT);

    prep_all<<<dim3(9, 4, NB * 128 + 1), dim3(32, 8)>>>(x, pw, w1, w2);
    main_kernel<<<dim3(NJ, NB), 512, SM_TOT>>>(b1, b2, out);
}